// round 8
// baseline (speedup 1.0000x reference)
#include <cuda_runtime.h>
#include <cuda_bf16.h>

#define BS   8
#define CH   256
#define TLEN 512
#define PBIN 16
#define SRAT 4

// 4 MB transposed-input scratch: (b, t, c) layout so channel gathers coalesce.
__device__ float g_tr[BS * TLEN * CH];

// ---------------------------------------------------------------------------
// Kernel 1: transpose (b, ch, t) -> (b, t, ch), 32x32 tiles, float4 both ways.
// ---------------------------------------------------------------------------
__global__ __launch_bounds__(256) void transpose_kernel(const float* __restrict__ in) {
    __shared__ float tile[32][33];
    const int b  = blockIdx.z;
    const int t0 = blockIdx.x * 32;
    const int c0 = blockIdx.y * 32;
    const int tx = threadIdx.x;          // 0..7  (float4 index)
    const int ty = threadIdx.y;          // 0..31

    const float* inb  = in   + (size_t)b * CH * TLEN;
    float*       outb = g_tr + (size_t)b * TLEN * CH;

    const float4 v = *(const float4*)&inb[(size_t)(c0 + ty) * TLEN + (t0 + 4 * tx)];
    tile[ty][4 * tx + 0] = v.x;
    tile[ty][4 * tx + 1] = v.y;
    tile[ty][4 * tx + 2] = v.z;
    tile[ty][4 * tx + 3] = v.w;
    __syncthreads();

    float4 w;
    w.x = tile[4 * tx + 0][ty];
    w.y = tile[4 * tx + 1][ty];
    w.z = tile[4 * tx + 2][ty];
    w.w = tile[4 * tx + 3][ty];
    *(float4*)&outb[(size_t)(t0 + ty) * CH + (c0 + 4 * tx)] = w;
}

// ---------------------------------------------------------------------------
// Kernel 2: TWO 64-thread blocks per ROI (half the channels each), 24 blocks
//   resident/SM. Thread owns 2 stride-64 channels; every gather is a one-line
//   scalar LDG.32.
//   NEW: dual gather mode, uniform per block.
//   - CONTIG (bin_size <= 8): per-bin weights over <=8 contiguous rows
//     (cnt typically 3-6) -> ~30% fewer LDG + FMA + LDS than per-sample.
//   - SAMPLE (bin_size > 8): rows are disjoint anyway; per-sample path.
//   Descriptor smem is a union (modes exclusive) to keep 24 blocks/SM.
// ---------------------------------------------------------------------------
#define S2 130

__global__ __launch_bounds__(64, 24) void roialign_kernel(const float* __restrict__ rois,
                                                          float4* __restrict__ out) {
    const int half = blockIdx.x & 1;         // which 128-channel half
    const int n    = blockIdx.x >> 1;        // ROI index
    const int l    = threadIdx.x;            // 0..63

    __shared__ union {
        uint4 desc[PBIN * SRAT];             // SAMPLE mode
        struct {                             // CONTIG mode
            float    w[PBIN][10];
            unsigned off[PBIN];
            int      cnt[PBIN];
        } c;
    } s_u;
    __shared__ float s_stage[PBIN * S2];     // [p][128 chans] stride-130 rows

    const float bf    = __ldg(&rois[n * 3 + 0]);
    const float start = __ldg(&rois[n * 3 + 1]);
    const float end   = __ldg(&rois[n * 3 + 2]);
    const float roi_len = fmaxf(end - start, 1.0f);
    const float bin     = roi_len * (1.0f / (float)PBIN);
    const int   b       = (int)bf;
    const bool  contig  = (bin <= 8.0f);     // uniform per block

    // ---- Phase A: descriptors ----
    if (contig) {
        if (l < PBIN) {
            const int p = l;
            float* wr = s_u.c.w[p];
            #pragma unroll
            for (int j = 0; j < 10; j++) wr[j] = 0.0f;

            const float x0  = start + ((float)p + 0.125f) * bin;
            const float xc0 = fminf(fmaxf(x0, 0.0f), (float)(TLEN - 1));
            const int   r0  = (int)floorf(xc0);
            int maxidx = 0;
            #pragma unroll
            for (int s = 0; s < SRAT; s++) {
                const float x = start + ((float)p + ((float)s + 0.5f) * 0.25f) * bin;
                const bool valid = (x >= -1.0f) && (x <= (float)TLEN);
                const float xc = fminf(fmaxf(x, 0.0f), (float)(TLEN - 1));
                const int xl = (int)floorf(xc);
                const int xh = min(xl + 1, TLEN - 1);
                const float lx = xc - (float)xl;
                wr[xl - r0] += valid ? (1.0f - lx) * 0.25f : 0.0f;
                wr[xh - r0] += valid ? lx * 0.25f : 0.0f;
                maxidx = max(maxidx, xh - r0);
            }
            s_u.c.cnt[p] = maxidx + 1;                       // <= 8
            s_u.c.off[p] = (unsigned)(((b << 9) + r0) << 10);
        }
    } else {
        const int p = l >> 2;                // bin
        const int s = l & 3;                 // sample
        const float x = start + ((float)p + ((float)s + 0.5f) * 0.25f) * bin;
        const bool valid = (x >= -1.0f) && (x <= (float)TLEN);
        const float xc = fminf(fmaxf(x, 0.0f), (float)(TLEN - 1));
        const int xl = (int)floorf(xc);
        const int xh = min(xl + 1, TLEN - 1);
        const float lx = xc - (float)xl;
        uint4 d;
        d.x = (unsigned)(((b << 9) + xl) << 10);
        d.y = (unsigned)(((b << 9) + xh) << 10);
        d.z = __float_as_uint(valid ? (1.0f - lx) * 0.25f : 0.0f);
        d.w = __float_as_uint(valid ? lx * 0.25f : 0.0f);
        s_u.desc[l] = d;
    }
    __syncthreads();

    // ---- Phase B: one-line scalar gathers, 2 strided channels/thread ----
    const char* base = (const char*)g_tr + (half * 128 + l) * 4;

    if (contig) {
        #pragma unroll 1
        for (int p = 0; p < PBIN; p++) {
            const unsigned off = s_u.c.off[p];
            const int      cnt = s_u.c.cnt[p];
            const float*   wr  = s_u.c.w[p];
            float a0 = 0.0f, a1 = 0.0f;
            #pragma unroll 2
            for (int j = 0; j < cnt; j++) {
                const float wj = wr[j];                       // broadcast LDS
                const float* r = (const float*)(base + off + (unsigned)j * 1024u);
                a0 += r[0]  * wj;                             // chan c0
                a1 += r[64] * wj;                             // chan c0+64
            }
            float* row = &s_stage[p * S2];
            row[l]      = a0;                 // bank (2p + l) % 32, conflict-free
            row[l + 64] = a1;
        }
    } else {
        #pragma unroll 1
        for (int p = 0; p < PBIN; p++) {
            float a0 = 0.0f, a1 = 0.0f;
            #pragma unroll
            for (int s = 0; s < SRAT; s++) {
                const uint4 d = s_u.desc[p * SRAT + s];
                const float wlo = __uint_as_float(d.z);
                const float whi = __uint_as_float(d.w);
                const float* lo = (const float*)(base + d.x);
                const float* hi = (const float*)(base + d.y);
                a0 += lo[0]  * wlo + hi[0]  * whi;
                a1 += lo[64] * wlo + hi[64] * whi;
            }
            float* row = &s_stage[p * S2];
            row[l]      = a0;
            row[l + 64] = a1;
        }
    }
    __syncthreads();

    // ---- Phase C: coalesced float4 writeback (contiguous half-ROI range) ----
    float4* outn = out + (size_t)n * (CH * PBIN / 4) + half * 512;

    #pragma unroll
    for (int k = 0; k < 8; k++) {
        const int q = l + 64 * k;            // 0..511, coalesced
        const int c = q >> 2;                // channel within half (0..127)
        const int g = q & 3;                 // bin-group
        float4 v;
        v.x = s_stage[(4 * g + 0) * S2 + c];
        v.y = s_stage[(4 * g + 1) * S2 + c];
        v.z = s_stage[(4 * g + 2) * S2 + c];
        v.w = s_stage[(4 * g + 3) * S2 + c];
        outn[q] = v;
    }
}

extern "C" void kernel_launch(void* const* d_in, const int* in_sizes, int n_in,
                              void* d_out, int out_size) {
    const float* input = (const float*)d_in[0];
    const float* rois  = (const float*)d_in[1];
    float4*      out   = (float4*)d_out;

    const int N = in_sizes[1] / 3;       // 2048 ROIs

    dim3 tgrid(TLEN / 32, CH / 32, BS);  // (16, 8, 8)
    dim3 tblk(8, 32);
    transpose_kernel<<<tgrid, tblk>>>(input);

    roialign_kernel<<<N * 2, 64>>>(rois, out);
}

// round 9
// speedup vs baseline: 1.0850x; 1.0850x over previous
#include <cuda_runtime.h>
#include <cuda_bf16.h>

#define BS   8
#define CH   256
#define TLEN 512
#define PBIN 16
#define SRAT 4

// 4 MB transposed-input scratch: (b, t, c) layout so channel gathers coalesce.
__device__ float g_tr[BS * TLEN * CH];

// ---------------------------------------------------------------------------
// Kernel 1: transpose (b, ch, t) -> (b, t, ch). 64x64 tiles, 256 threads,
// 4 float4 loads + 4 float4 stores per thread -> 256 fat blocks.
// ---------------------------------------------------------------------------
__global__ __launch_bounds__(256) void transpose_kernel(const float* __restrict__ in) {
    __shared__ float tile[64][65];
    const int b  = blockIdx.z;
    const int t0 = blockIdx.x * 64;
    const int c0 = blockIdx.y * 64;
    const int tx = threadIdx.x;          // 0..15 (float4 index)
    const int ty = threadIdx.y;          // 0..15

    const float* inb  = in   + (size_t)b * CH * TLEN;
    float*       outb = g_tr + (size_t)b * TLEN * CH;

    #pragma unroll
    for (int r = 0; r < 4; r++) {
        const int c = ty + 16 * r;
        const float4 v = *(const float4*)&inb[(size_t)(c0 + c) * TLEN + (t0 + 4 * tx)];
        tile[c][4 * tx + 0] = v.x;
        tile[c][4 * tx + 1] = v.y;
        tile[c][4 * tx + 2] = v.z;
        tile[c][4 * tx + 3] = v.w;
    }
    __syncthreads();
    #pragma unroll
    for (int r = 0; r < 4; r++) {
        const int t = ty + 16 * r;
        float4 w;
        w.x = tile[4 * tx + 0][t];
        w.y = tile[4 * tx + 1][t];
        w.z = tile[4 * tx + 2][t];
        w.w = tile[4 * tx + 3][t];
        *(float4*)&outb[(size_t)(t0 + t) * CH + (c0 + 4 * tx)] = w;
    }
}

// ---------------------------------------------------------------------------
// Kernel 2: R7 champion structure + balanced persistent grid.
//   4096 units (2 half-channel units per ROI), grid-stride over exactly
//   152*24 = 3648 resident blocks -> no second-wave tail.
//   Thread owns 2 stride-64 channels; every gather is a one-line scalar
//   LDG.32 in a FIXED fully-unrolled 8-load/bin loop (ptxas front-batches).
//   Loop-carried smem reuse is safe via the A-sync / B-sync pair.
// ---------------------------------------------------------------------------
#define S2 130
#define NUNITS (2048 * 2)
#define NBLK   (152 * 24)

__global__ __launch_bounds__(64, 24) void roialign_kernel(const float* __restrict__ rois,
                                                          float4* __restrict__ out) {
    const int l = threadIdx.x;               // 0..63

    __shared__ uint4 s_desc[PBIN * SRAT];    // 64 sample descriptors
    __shared__ float s_stage[PBIN * S2];     // [p][128 chans] stride-130 rows

    for (int u = blockIdx.x; u < NUNITS; u += NBLK) {
        const int half = u & 1;              // which 128-channel half
        const int n    = u >> 1;             // ROI index

        // ---- Phase A: per-sample descriptors (thread i == sample i) ----
        {
            const float bf    = __ldg(&rois[n * 3 + 0]);
            const float start = __ldg(&rois[n * 3 + 1]);
            const float end   = __ldg(&rois[n * 3 + 2]);
            const float roi_len = fmaxf(end - start, 1.0f);
            const float bin     = roi_len * (1.0f / (float)PBIN);

            const int p = l >> 2;            // bin
            const int s = l & 3;             // sample
            const float x = start + ((float)p + ((float)s + 0.5f) * 0.25f) * bin;
            const bool valid = (x >= -1.0f) && (x <= (float)TLEN);
            const float xc = fminf(fmaxf(x, 0.0f), (float)(TLEN - 1));
            const int xl = (int)floorf(xc);
            const int xh = min(xl + 1, TLEN - 1);
            const float lx = xc - (float)xl;
            const int b = (int)bf;

            uint4 d;
            d.x = (unsigned)(((b << 9) + xl) << 10);   // byte offset of row xl
            d.y = (unsigned)(((b << 9) + xh) << 10);   // byte offset of row xh
            d.z = __float_as_uint(valid ? (1.0f - lx) * 0.25f : 0.0f);
            d.w = __float_as_uint(valid ? lx * 0.25f : 0.0f);
            s_desc[l] = d;
        }
        __syncthreads();

        // ---- Phase B: one-line scalar gathers, 2 strided channels/thread ----
        const char* base = (const char*)g_tr + (half * 128 + l) * 4;

        #pragma unroll 1
        for (int p = 0; p < PBIN; p++) {
            float a0 = 0.0f, a1 = 0.0f;
            #pragma unroll
            for (int s = 0; s < SRAT; s++) {
                const uint4 d = s_desc[p * SRAT + s];
                const float wlo = __uint_as_float(d.z);
                const float whi = __uint_as_float(d.w);
                const float* lo = (const float*)(base + d.x);
                const float* hi = (const float*)(base + d.y);
                a0 += lo[0]  * wlo + hi[0]  * whi;   // chan c0
                a1 += lo[64] * wlo + hi[64] * whi;   // chan c0+64
            }
            float* row = &s_stage[p * S2];
            row[l]      = a0;                // bank (2p + l) % 32, conflict-free
            row[l + 64] = a1;
        }
        __syncthreads();

        // ---- Phase C: coalesced float4 writeback (contiguous half-ROI) ----
        float4* outn = out + (size_t)n * (CH * PBIN / 4) + half * 512;

        #pragma unroll
        for (int k = 0; k < 8; k++) {
            const int q = l + 64 * k;        // 0..511, coalesced
            const int c = q >> 2;            // channel within half (0..127)
            const int g = q & 3;             // bin-group
            float4 v;
            v.x = s_stage[(4 * g + 0) * S2 + c];
            v.y = s_stage[(4 * g + 1) * S2 + c];
            v.z = s_stage[(4 * g + 2) * S2 + c];
            v.w = s_stage[(4 * g + 3) * S2 + c];
            outn[q] = v;
        }
        // no trailing sync needed: next iteration's post-A sync orders
        // s_stage reuse (all warps must pass C before any warp enters B).
    }
}

extern "C" void kernel_launch(void* const* d_in, const int* in_sizes, int n_in,
                              void* d_out, int out_size) {
    const float* input = (const float*)d_in[0];
    const float* rois  = (const float*)d_in[1];
    float4*      out   = (float4*)d_out;

    dim3 tgrid(TLEN / 64, CH / 64, BS);  // (8, 4, 8) = 256 blocks
    dim3 tblk(16, 16);
    transpose_kernel<<<tgrid, tblk>>>(input);

    roialign_kernel<<<NBLK, 64>>>(rois, out);
}